// round 2
// baseline (speedup 1.0000x reference)
#include <cuda_runtime.h>

// Problem constants (fixed shapes from reference):
//   frames: [4, B=8, C=64, H=160, W=160] fp32
//   out:    [B, 4*C=256, H, W] fp32
// Math per pixel: out_i[c] = sum_j exp(v_i[c]*v_j[c]) * v_j[c] / Z_i,
//                 Z_i = sum_{j,c} exp(v_i[c]*v_j[c])
// exp matrix symmetric in (i,j): only 10 unique pairs.

#define HW_   25600   // 160*160
#define C_    64
#define B_    8
#define PX    32      // pixels per block
#define NSL   8       // channel slices (8 channels each)
#define NTHR  256

__device__ __forceinline__ float ex2f(float x) {
    float y;
    asm("ex2.approx.ftz.f32 %0, %1;" : "=f"(y) : "f"(x));
    return y;
}

__global__ __launch_bounds__(NTHR, 2)
void frame_attn_kernel(const float* __restrict__ frames, float* __restrict__ out)
{
    // sv: [j(4)][c(64)][px(32)]  -> 32 KB, conflict-free (px contiguous)
    __shared__ float sv[4 * C_ * PX];
    __shared__ float szp[NSL][4][PX];   // per-slice partial Z, 4 KB
    __shared__ float srz[4][PX];        // reciprocal Z, 512 B

    const int tid   = threadIdx.x;
    const int slice = tid >> 5;         // 0..7  (= warp id)
    const int px    = tid & 31;

    const int blocks_per_b = HW_ / PX;  // 800
    const int b  = blockIdx.x / blocks_per_b;
    const int p0 = (blockIdx.x % blocks_per_b) * PX;

    // ---- cooperative coalesced load: 4*64 rows of 32 contiguous floats ----
    const float* fb = frames + (size_t)b * C_ * HW_ + p0 + px;
    #pragma unroll
    for (int it = 0; it < (4 * C_ * PX) / NTHR; ++it) {
        int row = it * NSL + slice;     // 0..255 == j*64 + c
        int j = row >> 6;
        int c = row & 63;
        sv[row * PX + px] = fb[((size_t)j * B_ * C_ + c) * HW_];
    }
    __syncthreads();

    // ---- per-thread: 8 channels (slice*8 + k), all 4 frames ----
    const float* svb = sv + (slice * 8) * PX + px;   // base for this thread's channels

    float n[4][8];
    #pragma unroll
    for (int i = 0; i < 4; ++i)
        #pragma unroll
        for (int k = 0; k < 8; ++k) n[i][k] = 0.0f;

    float zp[10];
    #pragma unroll
    for (int p = 0; p < 10; ++p) zp[p] = 0.0f;

    const float LOG2E = 1.4426950408889634f;

    #pragma unroll
    for (int k = 0; k < 8; ++k) {
        float vk[4], wk[4];
        #pragma unroll
        for (int j = 0; j < 4; ++j) {
            float x = svb[(j * C_ + k) * PX];
            vk[j] = x;
            wk[j] = x * LOG2E;
        }
        int pi = 0;
        #pragma unroll
        for (int i = 0; i < 4; ++i) {
            #pragma unroll
            for (int j = i; j < 4; ++j) {
                float e = ex2f(wk[i] * vk[j]);
                zp[pi] += e;
                if (i == j) {
                    n[i][k] += e * vk[i];
                } else {
                    n[i][k] += e * vk[j];
                    n[j][k] += e * vk[i];
                }
                ++pi;
            }
        }
    }

    // combine pair sums -> per-head partial Z
    // pair index: (0,0)=0 (0,1)=1 (0,2)=2 (0,3)=3 (1,1)=4 (1,2)=5 (1,3)=6 (2,2)=7 (2,3)=8 (3,3)=9
    float z0 = zp[0] + zp[1] + zp[2] + zp[3];
    float z1 = zp[1] + zp[4] + zp[5] + zp[6];
    float z2 = zp[2] + zp[5] + zp[7] + zp[8];
    float z3 = zp[3] + zp[6] + zp[8] + zp[9];

    szp[slice][0][px] = z0;
    szp[slice][1][px] = z1;
    szp[slice][2][px] = z2;
    szp[slice][3][px] = z3;
    __syncthreads();

    // warps 0..3 reduce one head each across the 8 slices
    if (slice < 4) {
        float s = 0.0f;
        #pragma unroll
        for (int s8 = 0; s8 < NSL; ++s8) s += szp[s8][slice][px];
        srz[slice][px] = 1.0f / s;
    }
    __syncthreads();

    // ---- coalesced stores ----
    float* ob = out + ((size_t)b * 4 * C_ + slice * 8) * HW_ + p0 + px;
    #pragma unroll
    for (int i = 0; i < 4; ++i) {
        float r = srz[i][px];
        #pragma unroll
        for (int k = 0; k < 8; ++k) {
            ob[((size_t)i * C_ + k) * HW_] = n[i][k] * r;
        }
    }
}

extern "C" void kernel_launch(void* const* d_in, const int* in_sizes, int n_in,
                              void* d_out, int out_size)
{
    const float* frames = (const float*)d_in[0];
    float* out = (float*)d_out;
    const int nblocks = B_ * (HW_ / PX);   // 8 * 800 = 6400
    frame_attn_kernel<<<nblocks, NTHR>>>(frames, out);
}

// round 3
// speedup vs baseline: 1.0087x; 1.0087x over previous
#include <cuda_runtime.h>

// frames: [4, B=8, C=64, H=160, W=160] fp32 ; out: [B, 256, H, W] fp32
// out_i[c] = sum_j exp(v_i[c]*v_j[c]) * v_j[c] / Z_i,  Z_i = sum_{j,c} exp(v_i[c]*v_j[c])
// exp matrix symmetric in (i,j): 10 unique pairs.

#define HW_   25600   // 160*160
#define C_    64
#define B_    8
#define PX    32      // pixels per block
#define NSL   8       // channel slices (8 channels each)
#define NTHR  256
#define NROW  256     // 4 frames * 64 channels

__device__ __forceinline__ float ex2f(float x) {
    float y;
    asm("ex2.approx.ftz.f32 %0, %1;" : "=f"(y) : "f"(x));
    return y;
}

__global__ __launch_bounds__(NTHR, 4)
void frame_attn_kernel(const float* __restrict__ frames, float* __restrict__ out)
{
    // sv: [row(256)][px(32)] -> 32 KB. Input tile; overwritten in place with
    // unnormalized numerators during the compute loop (single owner per row/px).
    __shared__ float sv[NROW * PX];
    __shared__ float szp[NSL][4][PX];   // per-slice partial Z
    __shared__ float srz[4 * PX];       // reciprocal Z per (head, px)

    const int tid   = threadIdx.x;
    const int slice = tid >> 5;         // warp id, 0..7
    const int px    = tid & 31;

    const int blocks_per_b = HW_ / PX;  // 800
    const int b  = blockIdx.x / blocks_per_b;
    const int p0 = (blockIdx.x % blocks_per_b) * PX;

    // ---- vectorized cooperative load: 2048 float4s, 8 per thread ----
    // row r = j*64 + c  ->  frames[((j*B + b)*C + c)*HW + p0 + 4*col4]
    {
        const float4* fbase = (const float4*)(frames + p0);
        #pragma unroll
        for (int it = 0; it < (NROW * PX / 4) / NTHR; ++it) {
            int idx  = it * NTHR + tid;
            int row  = idx >> 3;
            int col4 = idx & 7;
            int j = row >> 6;
            int c = row & 63;
            float4 v = fbase[((size_t)(j * B_ + b) * C_ + c) * (HW_ / 4) + col4];
            *(float4*)(sv + row * PX + col4 * 4) = v;
        }
    }
    __syncthreads();

    // ---- compute: thread (slice, px) owns channels slice*8+k, k=0..7 ----
    const float* svb = sv + (slice * 8) * PX + px;

    float zp[10];
    #pragma unroll
    for (int p = 0; p < 10; ++p) zp[p] = 0.0f;

    const float LOG2E = 1.4426950408889634f;

    #pragma unroll
    for (int k = 0; k < 8; ++k) {
        float vk[4], wk[4];
        #pragma unroll
        for (int j = 0; j < 4; ++j) {
            float x = svb[(j * C_ + k) * PX];
            vk[j] = x;
            wk[j] = x * LOG2E;
        }
        float n4[4];
        // diagonal pairs initialize n4
        {
            float e0 = ex2f(wk[0] * vk[0]); zp[0] += e0; n4[0] = e0 * vk[0];
            float e1 = ex2f(wk[1] * vk[1]); zp[4] += e1; n4[1] = e1 * vk[1];
            float e2 = ex2f(wk[2] * vk[2]); zp[7] += e2; n4[2] = e2 * vk[2];
            float e3 = ex2f(wk[3] * vk[3]); zp[9] += e3; n4[3] = e3 * vk[3];
        }
        // off-diagonal pairs (symmetric)
        {
            float e;
            e = ex2f(wk[0] * vk[1]); zp[1] += e; n4[0] += e * vk[1]; n4[1] += e * vk[0];
            e = ex2f(wk[0] * vk[2]); zp[2] += e; n4[0] += e * vk[2]; n4[2] += e * vk[0];
            e = ex2f(wk[0] * vk[3]); zp[3] += e; n4[0] += e * vk[3]; n4[3] += e * vk[0];
            e = ex2f(wk[1] * vk[2]); zp[5] += e; n4[1] += e * vk[2]; n4[2] += e * vk[1];
            e = ex2f(wk[1] * vk[3]); zp[6] += e; n4[1] += e * vk[3]; n4[3] += e * vk[1];
            e = ex2f(wk[2] * vk[3]); zp[8] += e; n4[2] += e * vk[3]; n4[3] += e * vk[2];
        }
        // write unnormalized numerators back in place (row i*64 + slice*8 + k)
        #pragma unroll
        for (int i = 0; i < 4; ++i)
            sv[((i * C_ + slice * 8 + k)) * PX + px] = n4[i];
    }

    // per-head partial Z from pair sums
    // pairs: (0,0)=0 (0,1)=1 (0,2)=2 (0,3)=3 (1,1)=4 (1,2)=5 (1,3)=6 (2,2)=7 (2,3)=8 (3,3)=9
    szp[slice][0][px] = zp[0] + zp[1] + zp[2] + zp[3];
    szp[slice][1][px] = zp[1] + zp[4] + zp[5] + zp[6];
    szp[slice][2][px] = zp[2] + zp[5] + zp[7] + zp[8];
    szp[slice][3][px] = zp[3] + zp[6] + zp[8] + zp[9];
    __syncthreads();

    if (slice < 4) {
        float s = 0.0f;
        #pragma unroll
        for (int s8 = 0; s8 < NSL; ++s8) s += szp[s8][slice][px];
        srz[slice * PX + px] = 1.0f / s;
    }
    __syncthreads();

    // ---- vectorized store: scale by 1/Z, 8 float4s per thread ----
    {
        float4* obase = (float4*)(out + (size_t)b * 4 * C_ * HW_ + p0);
        #pragma unroll
        for (int it = 0; it < (NROW * PX / 4) / NTHR; ++it) {
            int idx  = it * NTHR + tid;
            int row  = idx >> 3;
            int col4 = idx & 7;
            int head = row >> 6;
            float4 n = *(const float4*)(sv + row * PX + col4 * 4);
            float4 r = *(const float4*)(srz + head * PX + col4 * 4);
            n.x *= r.x; n.y *= r.y; n.z *= r.z; n.w *= r.w;
            obase[(size_t)row * (HW_ / 4) + col4] = n;
        }
    }
}

extern "C" void kernel_launch(void* const* d_in, const int* in_sizes, int n_in,
                              void* d_out, int out_size)
{
    const float* frames = (const float*)d_in[0];
    float* out = (float*)d_out;
    const int nblocks = B_ * (HW_ / PX);   // 6400
    frame_attn_kernel<<<nblocks, NTHR>>>(frames, out);
}

// round 4
// speedup vs baseline: 1.0147x; 1.0060x over previous
#include <cuda_runtime.h>

// frames: [4, B=8, C=64, H=160, W=160] fp32 ; out: [B, 256, H, W] fp32
// out_i[c] = sum_j exp(v_i[c]*v_j[c]) * v_j[c] / Z_i,  Z_i = sum_{j,c} exp(v_i[c]*v_j[c])
// Symmetric in (i,j): 10 unique exp pairs per (pixel, channel).

#define HW_    25600   // 160*160
#define C_     64
#define B_     8
#define PX     32      // pixels per tile
#define NT     2       // tiles per block (consecutive -> contiguity + pipelining)
#define NTHR   256
#define NROW   256     // 4 frames * 64 channels
#define TILE_F (NROW * PX)   // 8192 floats = 32 KB

__device__ __forceinline__ float ex2f(float x) {
    float y;
    asm("ex2.approx.ftz.f32 %0, %1;" : "=f"(y) : "f"(x));
    return y;
}

__device__ __forceinline__ unsigned smem_u32(const void* p) {
    unsigned a;
    asm("{ .reg .u64 t; cvta.to.shared.u64 t, %1; cvt.u32.u64 %0, t; }"
        : "=r"(a) : "l"(p));
    return a;
}

__global__ __launch_bounds__(NTHR, 3)
void frame_attn_kernel(const float* __restrict__ frames, float* __restrict__ out)
{
    __shared__ float sbuf[2][TILE_F];   // double-buffered input tile / numerators
    __shared__ float szp[8][4][PX];     // per-slice partial Z
    __shared__ float srz[4 * PX];       // reciprocal Z per (head, px)

    const int tid   = threadIdx.x;
    const int slice = tid >> 5;          // warp id 0..7
    const int px    = tid & 31;
    const int r0    = tid >> 3;          // load-row base (0..31)
    const int c4b   = (tid & 7) * 16;    // byte offset within 128B row chunk

    const int tile0 = blockIdx.x * NT;   // 3200 blocks * 2 tiles; 800 tiles per b (even)

    // ---- async prefetch of one 32KB tile into sbuf[bufi] ----
    auto prefetch = [&](int tile, int bufi) {
        const int b  = tile / (HW_ / PX);
        const int p0 = (tile % (HW_ / PX)) * PX;
        const char* gbase = (const char*)frames
                          + (size_t)4 * p0 + (size_t)b * C_ * HW_ * 4 + c4b;
        const unsigned sb = smem_u32(&sbuf[bufi][0]) + (unsigned)(r0 * (PX * 4) + c4b);
        #pragma unroll
        for (int it = 0; it < 8; ++it) {
            const int row = it * 32 + r0;            // 0..255 = j*64 + c
            const int j = row >> 6, c = row & 63;
            const char* g = gbase + ((size_t)j * (B_ * C_) + c) * (HW_ * 4);
            const unsigned s = sb + (unsigned)(it * 32 * PX * 4);
            asm volatile("cp.async.cg.shared.global [%0], [%1], 16;"
                         :: "r"(s), "l"(g) : "memory");
        }
        asm volatile("cp.async.commit_group;" ::: "memory");
    };

    // ---- compute + normalize + store for the tile in sbuf[bufi] ----
    auto process = [&](int tile, int bufi) {
        float* sv = &sbuf[bufi][0];
        const int b  = tile / (HW_ / PX);
        const int p0 = (tile % (HW_ / PX)) * PX;

        const float* svb = sv + (slice * 8) * PX + px;
        const float LOG2E = 1.4426950408889634f;

        float zp[10];
        #pragma unroll
        for (int p = 0; p < 10; ++p) zp[p] = 0.0f;

        #pragma unroll
        for (int k = 0; k < 8; ++k) {
            float vk[4], wk[4];
            #pragma unroll
            for (int j = 0; j < 4; ++j) {
                float x = svb[(j * C_ + k) * PX];
                vk[j] = x;
                wk[j] = x * LOG2E;
            }
            float n4[4];
            {   // diagonal pairs
                float e0 = ex2f(wk[0] * vk[0]); zp[0] += e0; n4[0] = e0 * vk[0];
                float e1 = ex2f(wk[1] * vk[1]); zp[4] += e1; n4[1] = e1 * vk[1];
                float e2 = ex2f(wk[2] * vk[2]); zp[7] += e2; n4[2] = e2 * vk[2];
                float e3 = ex2f(wk[3] * vk[3]); zp[9] += e3; n4[3] = e3 * vk[3];
            }
            {   // symmetric off-diagonal pairs
                float e;
                e = ex2f(wk[0] * vk[1]); zp[1] += e; n4[0] += e * vk[1]; n4[1] += e * vk[0];
                e = ex2f(wk[0] * vk[2]); zp[2] += e; n4[0] += e * vk[2]; n4[2] += e * vk[0];
                e = ex2f(wk[0] * vk[3]); zp[3] += e; n4[0] += e * vk[3]; n4[3] += e * vk[0];
                e = ex2f(wk[1] * vk[2]); zp[5] += e; n4[1] += e * vk[2]; n4[2] += e * vk[1];
                e = ex2f(wk[1] * vk[3]); zp[6] += e; n4[1] += e * vk[3]; n4[3] += e * vk[1];
                e = ex2f(wk[2] * vk[3]); zp[8] += e; n4[2] += e * vk[3]; n4[3] += e * vk[2];
            }
            // unnormalized numerators back in place (row i*64 + slice*8 + k)
            #pragma unroll
            for (int i = 0; i < 4; ++i)
                sv[(i * C_ + slice * 8 + k) * PX + px] = n4[i];
        }

        // pairs: (0,0)=0 (0,1)=1 (0,2)=2 (0,3)=3 (1,1)=4 (1,2)=5 (1,3)=6 (2,2)=7 (2,3)=8 (3,3)=9
        szp[slice][0][px] = zp[0] + zp[1] + zp[2] + zp[3];
        szp[slice][1][px] = zp[1] + zp[4] + zp[5] + zp[6];
        szp[slice][2][px] = zp[2] + zp[5] + zp[7] + zp[8];
        szp[slice][3][px] = zp[3] + zp[6] + zp[8] + zp[9];
        __syncthreads();

        if (slice < 4) {
            float s = 0.0f;
            #pragma unroll
            for (int s8 = 0; s8 < 8; ++s8) s += szp[s8][slice][px];
            srz[slice * PX + px] = 1.0f / s;
        }
        __syncthreads();

        // vectorized streaming store: row = it*32 + r0, fixed 16B column c4b
        {
            char* obase = (char*)out + (size_t)b * 4 * C_ * HW_ * 4 + (size_t)4 * p0 + c4b;
            const float* svt = sv + r0 * PX;
            #pragma unroll
            for (int it = 0; it < 8; ++it) {
                const int row  = it * 32 + r0;
                const int head = row >> 6;
                float4 n = *(const float4*)(svt + it * 32 * PX + (c4b >> 2));
                float4 r = *(const float4*)(srz + head * PX + (c4b >> 2));
                n.x *= r.x; n.y *= r.y; n.z *= r.z; n.w *= r.w;
                __stcs((float4*)(obase + (size_t)row * (HW_ * 4)), n);
            }
        }
    };

    // ---- pipelined schedule: prefetch(t+1) overlaps process(t) ----
    prefetch(tile0, 0);
    prefetch(tile0 + 1, 1);

    asm volatile("cp.async.wait_group 1;" ::: "memory");
    __syncthreads();
    process(tile0, 0);

    asm volatile("cp.async.wait_group 0;" ::: "memory");
    __syncthreads();
    process(tile0 + 1, 1);
}

extern "C" void kernel_launch(void* const* d_in, const int* in_sizes, int n_in,
                              void* d_out, int out_size)
{
    const float* frames = (const float*)d_in[0];
    float* out = (float*)d_out;
    const int nblocks = B_ * (HW_ / PX) / NT;   // 3200
    frame_attn_kernel<<<nblocks, NTHR>>>(frames, out);
}